// round 1
// baseline (speedup 1.0000x reference)
#include <cuda_runtime.h>
#include <math.h>

#define BB   512
#define LLN  64
#define NEE  128
#define DD   128
#define NEGV (-9e15f)
#define NOUT ((size_t)BB * LLN * DD)   // 4194304

// Per-layer precomputed projection vectors (identical for all batches)
__device__ float g_u1[2][DD];   // w2 @ a[d:2d]   -> e1 = lrelu(qa + x.u1)
__device__ float g_u2[2][DD];   // w2 @ a2[0:d]   -> f1 = x.u2
__device__ float g_v3[2][DD];   // w3 @ a2[d:2d]  -> f2 = edge.v3
__device__ float g_qa[2];       // q . a[0:d]

__global__ void precompute_kernel(
    const float* __restrict__ w2_1, const float* __restrict__ w3_1,
    const float* __restrict__ q_1,  const float* __restrict__ a_1,  const float* __restrict__ a2_1,
    const float* __restrict__ w2_2, const float* __restrict__ w3_2,
    const float* __restrict__ q_2,  const float* __restrict__ a_2,  const float* __restrict__ a2_2)
{
    int k = threadIdx.x;  // 0..127
    const float* w2[2] = {w2_1, w2_2};
    const float* w3[2] = {w3_1, w3_2};
    const float* av[2] = {a_1,  a_2};
    const float* a2v[2] = {a2_1, a2_2};
    const float* qv[2] = {q_1,  q_2};

    for (int l = 0; l < 2; l++) {
        float u1 = 0.f, u2 = 0.f, v3 = 0.f;
        for (int j = 0; j < DD; j++) {
            float w2kj = w2[l][k * DD + j];
            u1 += w2kj * av[l][DD + j];
            u2 += w2kj * a2v[l][j];
            v3 += w3[l][k * DD + j] * a2v[l][DD + j];
        }
        g_u1[l][k] = u1;
        g_u2[l][k] = u2;
        g_v3[l][k] = v3;
    }

    __shared__ float red[DD];
    for (int l = 0; l < 2; l++) {
        red[k] = qv[l][k] * av[l][k];
        __syncthreads();
        if (k == 0) {
            float s = 0.f;
            for (int i = 0; i < DD; i++) s += red[i];
            g_qa[l] = s;
        }
        __syncthreads();
    }
}

// One CTA per batch item. 512 threads. Entire per-batch state in SMEM.
__global__ void __launch_bounds__(512, 1) session_main(
    const int*   __restrict__ inputs,   // [B, L]
    const float* __restrict__ HT,       // [B, NE, L]
    const float* __restrict__ emb,      // [V, D]
    const float* __restrict__ emb2,     // [V, D]
    const float* __restrict__ g2w,      // [D, D] transfer weight (layer 2)
    float*       __restrict__ out)      // [3 * B * L * D]
{
    extern __shared__ float sm[];
    float* xs    = sm;                  // [64][128] current node features
    float* resid = xs    + 64 * DD;     // [64][128] original embedding (residual)
    float* xt    = resid + 64 * DD;     // [64][128] transfer-projected features (layer 2)
    float* edge  = xt    + 64 * DD;     // [128][128] edge features
    float* att   = edge  + NEE * DD;    // 8192 floats: att_edge[128][64] / att_node[64][128] / weight staging
    float* e1    = att   + 8192;        // [64]
    float* f1    = e1    + 64;          // [64]
    float* f2    = f1    + 64;          // [128]
    unsigned long long* adjm = (unsigned long long*)(f2 + 128);  // [128] node bitmask per edge

    const int b  = blockIdx.x;
    const int t  = threadIdx.x;
    const int j8 = t >> 3, p8 = t & 7;  // 64 rows x 8 threads
    const int i4 = t >> 2, s4 = t & 3;  // 128 rows x 4 threads

    // ---- gather x = emb[inputs[b]] into xs and resid ----
    {
        int idx = inputs[b * LLN + j8];
        const float4* src = (const float4*)(emb + (size_t)idx * DD) + p8 * 4;
        float4* dx = (float4*)(xs    + j8 * DD) + p8 * 4;
        float4* dr = (float4*)(resid + j8 * DD) + p8 * 4;
        #pragma unroll
        for (int c = 0; c < 4; c++) { float4 v = src[c]; dx[c] = v; dr[c] = v; }
    }

    // ---- build per-edge node bitmasks from HT ----
    {
        const float* hrow = HT + ((size_t)b * NEE + i4) * LLN + s4 * 16;
        unsigned int bits = 0;
        #pragma unroll
        for (int c = 0; c < 16; c++) if (hrow[c] > 0.f) bits |= (1u << c);
        unsigned long long m = (unsigned long long)bits << (s4 * 16);
        m |= __shfl_xor_sync(0xffffffffu, m, 1, 4);
        m |= __shfl_xor_sync(0xffffffffu, m, 2, 4);
        if (s4 == 0) adjm[i4] = m;
    }
    __syncthreads();

    for (int l = 0; l < 2; l++) {
        const bool transfer = (l == 1);

        // ---- layer 2: xt = xs @ g2w  (K-tiled through att buffer as staging) ----
        if (transfer) {
            float acc[16];
            #pragma unroll
            for (int c = 0; c < 16; c++) acc[c] = 0.f;
            for (int k0 = 0; k0 < DD; k0 += 32) {
                __syncthreads();
                const float4* wsrc = (const float4*)(g2w + k0 * DD);
                float4* wdst = (float4*)att;
                wdst[t]       = wsrc[t];
                wdst[t + 512] = wsrc[t + 512];
                __syncthreads();
                #pragma unroll
                for (int kk = 0; kk < 32; kk++) {
                    float a = xs[j8 * DD + k0 + kk];
                    const float4* wr = (const float4*)(att + kk * DD + p8 * 16);
                    float4 w0 = wr[0], w1 = wr[1], w2 = wr[2], w3 = wr[3];
                    acc[0]  += a * w0.x; acc[1]  += a * w0.y; acc[2]  += a * w0.z; acc[3]  += a * w0.w;
                    acc[4]  += a * w1.x; acc[5]  += a * w1.y; acc[6]  += a * w1.z; acc[7]  += a * w1.w;
                    acc[8]  += a * w2.x; acc[9]  += a * w2.y; acc[10] += a * w2.z; acc[11] += a * w2.w;
                    acc[12] += a * w3.x; acc[13] += a * w3.y; acc[14] += a * w3.z; acc[15] += a * w3.w;
                }
            }
            __syncthreads();
            float* dst = xt + j8 * DD + p8 * 16;
            #pragma unroll
            for (int c = 0; c < 16; c++) dst[c] = acc[c];
            __syncthreads();
        }
        const float* xtp = transfer ? xt : xs;

        // ---- e1[j] = lrelu(qa + xs[j].u1),  f1[j] = xs[j].u2 ----
        {
            float s1 = 0.f, s2 = 0.f;
            const float* xrow = xs + j8 * DD + p8 * 16;
            const float* u1 = g_u1[l] + p8 * 16;
            const float* u2 = g_u2[l] + p8 * 16;
            #pragma unroll
            for (int c = 0; c < 16; c++) {
                float xv = xrow[c];
                s1 += xv * u1[c];
                s2 += xv * u2[c];
            }
            #pragma unroll
            for (int o = 4; o > 0; o >>= 1) {
                s1 += __shfl_down_sync(0xffffffffu, s1, o, 8);
                s2 += __shfl_down_sync(0xffffffffu, s2, o, 8);
            }
            if (p8 == 0) {
                float v = g_qa[l] + s1;
                e1[j8] = (v > 0.f) ? v : 0.2f * v;
                f1[j8] = s2;
            }
        }
        __syncthreads();

        // ---- att_edge[i][j] = masked softmax over nodes j of e1[j] ----
        {
            unsigned long long m = adjm[i4];
            float lg[16];
            float mx = NEGV;
            #pragma unroll
            for (int c = 0; c < 16; c++) {
                int j = s4 * 16 + c;
                float v = ((m >> j) & 1ull) ? e1[j] : NEGV;
                lg[c] = v;
                mx = fmaxf(mx, v);
            }
            mx = fmaxf(mx, __shfl_xor_sync(0xffffffffu, mx, 1, 4));
            mx = fmaxf(mx, __shfl_xor_sync(0xffffffffu, mx, 2, 4));
            float sum = 0.f;
            #pragma unroll
            for (int c = 0; c < 16; c++) {
                float p = __expf(lg[c] - mx);
                lg[c] = p;
                sum += p;
            }
            sum += __shfl_xor_sync(0xffffffffu, sum, 1, 4);
            sum += __shfl_xor_sync(0xffffffffu, sum, 2, 4);
            float inv = 1.f / sum;
            #pragma unroll
            for (int c = 0; c < 16; c++) att[i4 * 64 + s4 * 16 + c] = lg[c] * inv;
        }
        __syncthreads();

        // ---- edge = att_edge @ xt,  fused f2[i] = edge[i].v3 ----
        {
            float acc[32];
            #pragma unroll
            for (int c = 0; c < 32; c++) acc[c] = 0.f;
            const int cb = s4 * 32;
            for (int j = 0; j < 64; j++) {
                float p = att[i4 * 64 + j];
                const float4* xr = (const float4*)(xtp + j * DD + cb);
                #pragma unroll
                for (int q = 0; q < 8; q++) {
                    float4 v = xr[q];
                    acc[q * 4 + 0] += p * v.x;
                    acc[q * 4 + 1] += p * v.y;
                    acc[q * 4 + 2] += p * v.z;
                    acc[q * 4 + 3] += p * v.w;
                }
            }
            float4* er = (float4*)(edge + i4 * DD + cb);
            #pragma unroll
            for (int q = 0; q < 8; q++)
                er[q] = make_float4(acc[q * 4], acc[q * 4 + 1], acc[q * 4 + 2], acc[q * 4 + 3]);
            float s2 = 0.f;
            const float* v3 = g_v3[l] + cb;
            #pragma unroll
            for (int c = 0; c < 32; c++) s2 += acc[c] * v3[c];
            s2 += __shfl_xor_sync(0xffffffffu, s2, 1, 4);
            s2 += __shfl_xor_sync(0xffffffffu, s2, 2, 4);
            if (s4 == 0) f2[i4] = s2;
        }
        __syncthreads();

        // ---- att_node[j][i] = masked softmax over edges i of lrelu(f1[j] + f2[i]) ----
        {
            float f1j = f1[j8];
            float lg[16];
            float mx = NEGV;
            #pragma unroll
            for (int c = 0; c < 16; c++) {
                int i = p8 * 16 + c;
                float v = f1j + f2[i];
                v = (v > 0.f) ? v : 0.2f * v;
                bool mm = (adjm[i] >> j8) & 1ull;
                v = mm ? v : NEGV;
                lg[c] = v;
                mx = fmaxf(mx, v);
            }
            #pragma unroll
            for (int o = 4; o > 0; o >>= 1)
                mx = fmaxf(mx, __shfl_xor_sync(0xffffffffu, mx, o, 8));
            float sum = 0.f;
            #pragma unroll
            for (int c = 0; c < 16; c++) {
                float p = __expf(lg[c] - mx);
                lg[c] = p;
                sum += p;
            }
            #pragma unroll
            for (int o = 4; o > 0; o >>= 1)
                sum += __shfl_xor_sync(0xffffffffu, sum, o, 8);
            float inv = 1.f / sum;
            #pragma unroll
            for (int c = 0; c < 16; c++) att[j8 * 128 + p8 * 16 + c] = lg[c] * inv;
        }
        __syncthreads();

        // ---- node = att_node @ edge; xs = node + resid ----
        {
            float acc[16];
            #pragma unroll
            for (int c = 0; c < 16; c++) acc[c] = 0.f;
            const int cb = p8 * 16;
            for (int i = 0; i < NEE; i++) {
                float p = att[j8 * 128 + i];
                const float4* er = (const float4*)(edge + i * DD + cb);
                #pragma unroll
                for (int q = 0; q < 4; q++) {
                    float4 v = er[q];
                    acc[q * 4 + 0] += p * v.x;
                    acc[q * 4 + 1] += p * v.y;
                    acc[q * 4 + 2] += p * v.z;
                    acc[q * 4 + 3] += p * v.w;
                }
            }
            float* dst = xs + j8 * DD + cb;
            const float* rs = resid + j8 * DD + cb;
            #pragma unroll
            for (int c = 0; c < 16; c++) dst[c] = acc[c] + rs[c];
        }
        __syncthreads();
    }

    // ---- outputs: x, x, emb2[inputs] ----
    {
        const size_t base = ((size_t)b * LLN + j8) * (size_t)DD + p8 * 16;
        const float4* xr = (const float4*)(xs + j8 * DD + p8 * 16);
        float4* o1 = (float4*)(out + base);
        float4* o2 = (float4*)(out + NOUT + base);
        int idx = inputs[b * LLN + j8];
        const float4* s2 = (const float4*)(emb2 + (size_t)idx * DD) + p8 * 4;
        float4* o3 = (float4*)(out + 2 * NOUT + base);
        #pragma unroll
        for (int c = 0; c < 4; c++) {
            float4 v = xr[c];
            o1[c] = v;
            o2[c] = v;
            o3[c] = s2[c];
        }
    }
}

extern "C" void kernel_launch(void* const* d_in, const int* in_sizes, int n_in,
                              void* d_out, int out_size) {
    (void)in_sizes; (void)n_in; (void)out_size;
    const int*   inputs = (const int*)  d_in[0];
    const float* HT     = (const float*)d_in[1];
    // d_in[2] = G, d_in[3] = EG : unused by forward
    const float* emb    = (const float*)d_in[4];
    const float* emb2   = (const float*)d_in[5];
    const float* g1_w2  = (const float*)d_in[6];
    const float* g1_w3  = (const float*)d_in[7];
    const float* g1_q   = (const float*)d_in[8];
    const float* g1_a   = (const float*)d_in[9];
    const float* g1_a2  = (const float*)d_in[10];
    const float* g2_w   = (const float*)d_in[11];
    const float* g2_w2  = (const float*)d_in[12];
    const float* g2_w3  = (const float*)d_in[13];
    const float* g2_q   = (const float*)d_in[14];
    const float* g2_a   = (const float*)d_in[15];
    const float* g2_a2  = (const float*)d_in[16];
    float* out = (float*)d_out;

    const size_t smem =
        (size_t)(64 * DD * 3 + NEE * DD + 8192 + 64 + 64 + 128) * sizeof(float)
        + 128 * sizeof(unsigned long long);

    cudaFuncSetAttribute(session_main, cudaFuncAttributeMaxDynamicSharedMemorySize, (int)smem);

    precompute_kernel<<<1, 128>>>(g1_w2, g1_w3, g1_q, g1_a, g1_a2,
                                  g2_w2, g2_w3, g2_q, g2_a, g2_a2);
    session_main<<<BB, 512, smem>>>(inputs, HT, emb, emb2, g2_w, out);
}

// round 3
// speedup vs baseline: 5.8515x; 5.8515x over previous
#include <cuda_runtime.h>
#include <math.h>

#define BB   512
#define LLN  64
#define NEE  128
#define DD   128
#define NEGV (-9e15f)
#define NOUT ((size_t)BB * LLN * DD)

// smem layout (float offsets)
#define OFF_XS   0
#define OFF_XT   8192
#define OFF_EDGE 16384          // 128x128; also stages g2w in layer 2
#define OFF_ATT  32768          // dup-packed attention: 16384 floats
#define OFF_E1   49152
#define OFF_F1   49216
#define OFF_F2   49280
#define OFF_ADJ  49408          // u64[128]
#define SMEM_BYTES ((49408 + 256) * 4)

// Per-layer precomputed projection vectors
__device__ float g_u1[2][DD];   // w2 @ a[d:2d]
__device__ float g_u2[2][DD];   // w2 @ a2[0:d]
__device__ float g_v3[2][DD];   // w3 @ a2[d:2d]
__device__ float g_qa[2];       // q . a[0:d]

__global__ void precompute_kernel(
    const float* __restrict__ w2_1, const float* __restrict__ w3_1,
    const float* __restrict__ q_1,  const float* __restrict__ a_1,  const float* __restrict__ a2_1,
    const float* __restrict__ w2_2, const float* __restrict__ w3_2,
    const float* __restrict__ q_2,  const float* __restrict__ a_2,  const float* __restrict__ a2_2)
{
    int k = threadIdx.x;  // 0..127
    const float* w2[2]  = {w2_1, w2_2};
    const float* w3[2]  = {w3_1, w3_2};
    const float* av[2]  = {a_1,  a_2};
    const float* a2v[2] = {a2_1, a2_2};
    const float* qv[2]  = {q_1,  q_2};

    for (int l = 0; l < 2; l++) {
        float u1 = 0.f, u2 = 0.f, v3 = 0.f;
        for (int j = 0; j < DD; j++) {
            float w2kj = w2[l][k * DD + j];
            u1 += w2kj * av[l][DD + j];
            u2 += w2kj * a2v[l][j];
            v3 += w3[l][k * DD + j] * a2v[l][DD + j];
        }
        g_u1[l][k] = u1;
        g_u2[l][k] = u2;
        g_v3[l][k] = v3;
    }
    __shared__ float red[DD];
    for (int l = 0; l < 2; l++) {
        red[k] = qv[l][k] * av[l][k];
        __syncthreads();
        if (k == 0) {
            float s = 0.f;
            for (int i = 0; i < DD; i++) s += red[i];
            g_qa[l] = s;
        }
        __syncthreads();
    }
}

// ---- packed fp32x2 helpers (Blackwell) ----
__device__ __forceinline__ unsigned long long fma2(unsigned long long a, unsigned long long b,
                                                   unsigned long long c) {
    unsigned long long d;
    asm("fma.rn.f32x2 %0, %1, %2, %3;" : "=l"(d) : "l"(a), "l"(b), "l"(c));
    return d;
}
__device__ __forceinline__ unsigned long long dup2(float x) {
    unsigned long long d;
    asm("mov.b64 %0, {%1, %2};" : "=l"(d) : "f"(x), "f"(x));
    return d;
}
__device__ __forceinline__ float2 unp2(unsigned long long a) {
    float lo, hi;
    asm("mov.b64 {%0, %1}, %2;" : "=f"(lo), "=f"(hi) : "l"(a));
    return make_float2(lo, hi);
}
__device__ __forceinline__ float wredsum(float v) {
    #pragma unroll
    for (int o = 16; o > 0; o >>= 1) v += __shfl_xor_sync(0xffffffffu, v, o);
    return v;
}
__device__ __forceinline__ float wredmax(float v) {
    #pragma unroll
    for (int o = 16; o > 0; o >>= 1) v = fmaxf(v, __shfl_xor_sync(0xffffffffu, v, o));
    return v;
}

// One CTA per batch item. 512 threads = 16 warps. Warp-per-row everywhere:
// every smem vector access is one warp reading one 512B row -> conflict-free.
__global__ void __launch_bounds__(512, 1) session_main(
    const int*   __restrict__ inputs,   // [B, L]
    const float* __restrict__ HT,       // [B, NE, L]
    const float* __restrict__ emb,      // [V, D]
    const float* __restrict__ emb2,     // [V, D]
    const float* __restrict__ g2w,      // [D, D]
    float*       __restrict__ out)
{
    extern __shared__ float sm[];
    float* xs   = sm + OFF_XS;
    float* xt   = sm + OFF_XT;
    float* edge = sm + OFF_EDGE;
    float* att  = sm + OFF_ATT;
    float* e1   = sm + OFF_E1;
    float* f1   = sm + OFF_F1;
    float* f2   = sm + OFF_F2;
    unsigned long long* adjm = (unsigned long long*)(sm + OFF_ADJ);

    const int b = blockIdx.x;
    const int t = threadIdx.x;
    const int w = t >> 5, lane = t & 31;

    // ---- P0: gather x = emb[inputs[b]]; warp w owns rows 4w..4w+3 ----
    #pragma unroll
    for (int r = 0; r < 4; r++) {
        int row = w * 4 + r;
        int idx = __ldg(inputs + b * LLN + row);
        float4 v = __ldg((const float4*)(emb + (size_t)idx * DD) + lane);
        *((float4*)(xs + row * DD) + lane) = v;
    }

    // ---- P1: per-edge node bitmasks via ballot; warp w owns edges 8w..8w+7 ----
    #pragma unroll
    for (int k = 0; k < 8; k++) {
        int e = w * 8 + k;
        const float* hr = HT + ((size_t)b * NEE + e) * LLN;
        float h0 = __ldg(hr + lane), h1 = __ldg(hr + lane + 32);
        unsigned m0 = __ballot_sync(0xffffffffu, h0 > 0.f);
        unsigned m1 = __ballot_sync(0xffffffffu, h1 > 0.f);
        if (lane == 0) adjm[e] = ((unsigned long long)m1 << 32) | (unsigned long long)m0;
    }
    __syncthreads();

    for (int l = 0; l < 2; l++) {
        const float* xtp = xs;

        if (l == 1) {
            // stage g2w into the (currently dead) edge buffer
            {
                const float4* src = (const float4*)g2w;
                float4* dst = (float4*)edge;
                #pragma unroll
                for (int r = 0; r < 8; r++)
                    dst[w * 256 + r * 32 + lane] = __ldg(src + w * 256 + r * 32 + lane);
            }
            __syncthreads();
            // transfer GEMM: xt = xs @ W ; warp owns rows 4w..4w+3
            unsigned long long acc[4][2];
            #pragma unroll
            for (int r = 0; r < 4; r++) { acc[r][0] = 0; acc[r][1] = 0; }
            #pragma unroll 2
            for (int k = 0; k < DD; k++) {
                ulonglong2 wv = *((const ulonglong2*)(edge + k * DD) + lane);
                #pragma unroll
                for (int r = 0; r < 4; r++) {
                    unsigned long long s = dup2(xs[(w * 4 + r) * DD + k]);
                    acc[r][0] = fma2(s, wv.x, acc[r][0]);
                    acc[r][1] = fma2(s, wv.y, acc[r][1]);
                }
            }
            __syncthreads();
            #pragma unroll
            for (int r = 0; r < 4; r++) {
                ulonglong2 o; o.x = acc[r][0]; o.y = acc[r][1];
                *((ulonglong2*)(xt + (w * 4 + r) * DD) + lane) = o;
            }
            __syncthreads();
            xtp = xt;
        }

        // ---- P2a: e1[j] = lrelu(qa + xs[j].u1), f1[j] = xs[j].u2 ----
        {
            float4 u1v = ((const float4*)g_u1[l])[lane];
            float4 u2v = ((const float4*)g_u2[l])[lane];
            float qa = g_qa[l];
            #pragma unroll
            for (int r = 0; r < 4; r++) {
                int row = w * 4 + r;
                float4 x4 = *((const float4*)(xs + row * DD) + lane);
                float s1 = x4.x * u1v.x + x4.y * u1v.y + x4.z * u1v.z + x4.w * u1v.w;
                float s2 = x4.x * u2v.x + x4.y * u2v.y + x4.z * u2v.z + x4.w * u2v.w;
                s1 = wredsum(s1);
                s2 = wredsum(s2);
                if (lane == 0) {
                    float v = qa + s1;
                    e1[row] = (v > 0.f) ? v : 0.2f * v;
                    f1[row] = s2;
                }
            }
        }
        __syncthreads();

        // ---- P2b: att_edge softmax, stored dup-packed att[(e*64+j)*2 + {0,1}] ----
        {
            float ev0 = e1[lane], ev1 = e1[lane + 32];
            #pragma unroll
            for (int k = 0; k < 8; k++) {
                int e = w * 8 + k;
                unsigned long long m = adjm[e];
                float v0 = ((m >> lane) & 1ull) ? ev0 : NEGV;
                float v1 = ((m >> (lane + 32)) & 1ull) ? ev1 : NEGV;
                float mx = wredmax(fmaxf(v0, v1));
                float p0 = __expf(v0 - mx), p1 = __expf(v1 - mx);
                float inv = 1.f / wredsum(p0 + p1);
                p0 *= inv; p1 *= inv;
                *((float2*)(att + (e * 64 + lane) * 2))        = make_float2(p0, p0);
                *((float2*)(att + (e * 64 + lane + 32) * 2))   = make_float2(p1, p1);
            }
        }
        __syncthreads();

        // ---- P2c: edge = att_edge @ xtp (fma2), fused f2 = edge . v3 ----
        {
            unsigned long long acc[8][2];
            #pragma unroll
            for (int k = 0; k < 8; k++) { acc[k][0] = 0; acc[k][1] = 0; }
            const int e0 = w * 8;
            #pragma unroll 2
            for (int j = 0; j < LLN; j++) {
                ulonglong2 xv = *((const ulonglong2*)(xtp + j * DD) + lane);
                #pragma unroll
                for (int k = 0; k < 8; k++) {
                    unsigned long long a2 =
                        *((const unsigned long long*)(att + ((e0 + k) * 64 + j) * 2));
                    acc[k][0] = fma2(a2, xv.x, acc[k][0]);
                    acc[k][1] = fma2(a2, xv.y, acc[k][1]);
                }
            }
            float4 v3v = ((const float4*)g_v3[l])[lane];
            #pragma unroll
            for (int k = 0; k < 8; k++) {
                ulonglong2 o; o.x = acc[k][0]; o.y = acc[k][1];
                *((ulonglong2*)(edge + (e0 + k) * DD) + lane) = o;
                float2 lo = unp2(acc[k][0]), hi = unp2(acc[k][1]);
                float s = lo.x * v3v.x + lo.y * v3v.y + hi.x * v3v.z + hi.y * v3v.w;
                s = wredsum(s);
                if (lane == 0) f2[e0 + k] = s;
            }
        }
        __syncthreads();

        // ---- P2d: att_node softmax, stored dup-packed att[(j*128+i)*2 + {0,1}] ----
        {
            unsigned long long mk0 = adjm[lane],      mk1 = adjm[lane + 32];
            unsigned long long mk2 = adjm[lane + 64], mk3 = adjm[lane + 96];
            float fv0 = f2[lane], fv1 = f2[lane + 32], fv2 = f2[lane + 64], fv3 = f2[lane + 96];
            #pragma unroll
            for (int r = 0; r < 4; r++) {
                int j = w * 4 + r;
                float f1j = f1[j];
                float z0 = f1j + fv0; z0 = (z0 > 0.f) ? z0 : 0.2f * z0;
                float z1 = f1j + fv1; z1 = (z1 > 0.f) ? z1 : 0.2f * z1;
                float z2 = f1j + fv2; z2 = (z2 > 0.f) ? z2 : 0.2f * z2;
                float z3 = f1j + fv3; z3 = (z3 > 0.f) ? z3 : 0.2f * z3;
                float v0 = ((mk0 >> j) & 1ull) ? z0 : NEGV;
                float v1 = ((mk1 >> j) & 1ull) ? z1 : NEGV;
                float v2 = ((mk2 >> j) & 1ull) ? z2 : NEGV;
                float v3 = ((mk3 >> j) & 1ull) ? z3 : NEGV;
                float mx = wredmax(fmaxf(fmaxf(v0, v1), fmaxf(v2, v3)));
                float p0 = __expf(v0 - mx), p1 = __expf(v1 - mx);
                float p2 = __expf(v2 - mx), p3 = __expf(v3 - mx);
                float inv = 1.f / wredsum(p0 + p1 + p2 + p3);
                p0 *= inv; p1 *= inv; p2 *= inv; p3 *= inv;
                *((float2*)(att + (j * 128 + lane) * 2))      = make_float2(p0, p0);
                *((float2*)(att + (j * 128 + lane + 32) * 2)) = make_float2(p1, p1);
                *((float2*)(att + (j * 128 + lane + 64) * 2)) = make_float2(p2, p2);
                *((float2*)(att + (j * 128 + lane + 96) * 2)) = make_float2(p3, p3);
            }
        }
        __syncthreads();

        // ---- P2e: x = att_node @ edge + residual(emb gather) ----
        {
            unsigned long long acc[4][2];
            #pragma unroll
            for (int r = 0; r < 4; r++) { acc[r][0] = 0; acc[r][1] = 0; }
            const int j0 = w * 4;
            #pragma unroll 2
            for (int i = 0; i < NEE; i++) {
                ulonglong2 ev = *((const ulonglong2*)(edge + i * DD) + lane);
                #pragma unroll
                for (int r = 0; r < 4; r++) {
                    unsigned long long a2 =
                        *((const unsigned long long*)(att + ((j0 + r) * 128 + i) * 2));
                    acc[r][0] = fma2(a2, ev.x, acc[r][0]);
                    acc[r][1] = fma2(a2, ev.y, acc[r][1]);
                }
            }
            #pragma unroll
            for (int r = 0; r < 4; r++) {
                int row = j0 + r;
                int idx = __ldg(inputs + b * LLN + row);
                float4 g = __ldg((const float4*)(emb + (size_t)idx * DD) + lane);
                float2 lo = unp2(acc[r][0]), hi = unp2(acc[r][1]);
                float4 o = make_float4(lo.x + g.x, lo.y + g.y, hi.x + g.z, hi.y + g.w);
                *((float4*)(xs + row * DD) + lane) = o;
            }
        }
        __syncthreads();
    }

    // ---- outputs: x, x, emb2[inputs] ----
    #pragma unroll
    for (int r = 0; r < 4; r++) {
        int row = w * 4 + r;
        size_t base = ((size_t)b * LLN + row) * (size_t)DD + lane * 4;
        float4 v = *((const float4*)(xs + row * DD) + lane);
        *(float4*)(out + base) = v;
        *(float4*)(out + NOUT + base) = v;
        int idx = __ldg(inputs + b * LLN + row);
        float4 g = __ldg((const float4*)(emb2 + (size_t)idx * DD) + lane);
        *(float4*)(out + 2 * NOUT + base) = g;
    }
}

extern "C" void kernel_launch(void* const* d_in, const int* in_sizes, int n_in,
                              void* d_out, int out_size) {
    (void)in_sizes; (void)n_in; (void)out_size;
    const int*   inputs = (const int*)  d_in[0];
    const float* HT     = (const float*)d_in[1];
    const float* emb    = (const float*)d_in[4];
    const float* emb2   = (const float*)d_in[5];
    const float* g1_w2  = (const float*)d_in[6];
    const float* g1_w3  = (const float*)d_in[7];
    const float* g1_q   = (const float*)d_in[8];
    const float* g1_a   = (const float*)d_in[9];
    const float* g1_a2  = (const float*)d_in[10];
    const float* g2_w   = (const float*)d_in[11];
    const float* g2_w2  = (const float*)d_in[12];
    const float* g2_w3  = (const float*)d_in[13];
    const float* g2_q   = (const float*)d_in[14];
    const float* g2_a   = (const float*)d_in[15];
    const float* g2_a2  = (const float*)d_in[16];
    float* out = (float*)d_out;

    cudaFuncSetAttribute(session_main, cudaFuncAttributeMaxDynamicSharedMemorySize, SMEM_BYTES);

    precompute_kernel<<<1, 128>>>(g1_w2, g1_w3, g1_q, g1_a, g1_a2,
                                  g2_w2, g2_w3, g2_q, g2_a, g2_a2);
    session_main<<<BB, 512, SMEM_BYTES>>>(inputs, HT, emb, emb2, g2_w, out);
}

// round 4
// speedup vs baseline: 6.2588x; 1.0696x over previous
#include <cuda_runtime.h>
#include <math.h>

#define BB   512
#define LLN  64
#define NEE  128
#define DD   128
#define NEGV (-9e15f)
#define NOUT ((size_t)BB * LLN * DD)

// smem layout (float offsets)
#define OFF_XS    0              // 8192 : x (64x128)
#define OFF_XT    8192           // 8192 : transferred x (64x128)
#define OFF_EDGE  16384          // 16384: edge (128x128), also stages g2w
#define OFF_ATT   32768          // 8448 : att1[64][130] / att2[128][66] / scratch(4096 u64)
#define OFF_E1    41216          // 64
#define OFF_F1    41280          // 64
#define OFF_F2    41344          // 128
#define OFF_ADJ   41472          // u64[128] (256 floats)
#define SMEM_BYTES ((41728 + 32) * 4)

#define P1PITCH 130              // att1 row pitch (floats)
#define P2PITCH 66               // att2 row pitch (floats)

typedef unsigned long long u64;

// Per-layer precomputed projection vectors
__device__ float g_u1[2][DD];   // w2 @ a[d:2d]
__device__ float g_u2[2][DD];   // w2 @ a2[0:d]
__device__ float g_v3[2][DD];   // w3 @ a2[d:2d]
__device__ float g_qa[2];       // q . a[0:d]

__global__ void precompute_kernel(
    const float* __restrict__ w2_1, const float* __restrict__ w3_1,
    const float* __restrict__ q_1,  const float* __restrict__ a_1,  const float* __restrict__ a2_1,
    const float* __restrict__ w2_2, const float* __restrict__ w3_2,
    const float* __restrict__ q_2,  const float* __restrict__ a_2,  const float* __restrict__ a2_2)
{
    int k = threadIdx.x;  // 0..127
    const float* w2[2]  = {w2_1, w2_2};
    const float* w3[2]  = {w3_1, w3_2};
    const float* av[2]  = {a_1,  a_2};
    const float* a2v[2] = {a2_1, a2_2};
    const float* qv[2]  = {q_1,  q_2};

    for (int l = 0; l < 2; l++) {
        float u1 = 0.f, u2 = 0.f, v3 = 0.f;
        for (int j = 0; j < DD; j++) {
            float w2kj = w2[l][k * DD + j];
            u1 += w2kj * av[l][DD + j];
            u2 += w2kj * a2v[l][j];
            v3 += w3[l][k * DD + j] * a2v[l][DD + j];
        }
        g_u1[l][k] = u1;
        g_u2[l][k] = u2;
        g_v3[l][k] = v3;
    }
    __shared__ float red[DD];
    for (int l = 0; l < 2; l++) {
        red[k] = qv[l][k] * av[l][k];
        __syncthreads();
        if (k == 0) {
            float s = 0.f;
            for (int i = 0; i < DD; i++) s += red[i];
            g_qa[l] = s;
        }
        __syncthreads();
    }
}

// ---- packed fp32x2 helpers ----
__device__ __forceinline__ u64 fma2(u64 a, u64 b, u64 c) {
    u64 d;
    asm("fma.rn.f32x2 %0, %1, %2, %3;" : "=l"(d) : "l"(a), "l"(b), "l"(c));
    return d;
}
__device__ __forceinline__ u64 add2(u64 a, u64 b) {
    u64 d;
    asm("add.rn.f32x2 %0, %1, %2;" : "=l"(d) : "l"(a), "l"(b));
    return d;
}
__device__ __forceinline__ u64 dup2(float x) {
    u64 d;
    asm("mov.b64 %0, {%1, %2};" : "=l"(d) : "f"(x), "f"(x));
    return d;
}
__device__ __forceinline__ u64 pk2(float lo, float hi) {
    u64 d;
    asm("mov.b64 %0, {%1, %2};" : "=l"(d) : "f"(lo), "f"(hi));
    return d;
}
__device__ __forceinline__ float2 unp2(u64 a) {
    float lo, hi;
    asm("mov.b64 {%0, %1}, %2;" : "=f"(lo), "=f"(hi) : "l"(a));
    return make_float2(lo, hi);
}
__device__ __forceinline__ float wredsum(float v) {
    #pragma unroll
    for (int o = 16; o > 0; o >>= 1) v += __shfl_xor_sync(0xffffffffu, v, o);
    return v;
}
__device__ __forceinline__ float wredmax(float v) {
    #pragma unroll
    for (int o = 16; o > 0; o >>= 1) v = fmaxf(v, __shfl_xor_sync(0xffffffffu, v, o));
    return v;
}
__device__ __forceinline__ u64 wredsum2(u64 v) {
    #pragma unroll
    for (int o = 16; o > 0; o >>= 1) v = add2(v, __shfl_xor_sync(0xffffffffu, v, o));
    return v;
}

// One CTA per batch item, 512 threads = 16 warps.
__global__ void __launch_bounds__(512, 1) session_main(
    const int*   __restrict__ inputs,   // [B, L]
    const float* __restrict__ HT,       // [B, NE, L]
    const float* __restrict__ emb,      // [V, D]
    const float* __restrict__ emb2,     // [V, D]
    const float* __restrict__ g2w,      // [D, D]
    float*       __restrict__ out)
{
    extern __shared__ float sm[];
    float* xs   = sm + OFF_XS;
    float* xt   = sm + OFF_XT;
    float* edge = sm + OFF_EDGE;
    float* att  = sm + OFF_ATT;
    float* e1   = sm + OFF_E1;
    float* f1   = sm + OFF_F1;
    float* f2   = sm + OFF_F2;
    u64*   adjm = (u64*)(sm + OFF_ADJ);
    u64*   scr  = (u64*)att;            // 4096 u64 scratch (reused after att dead)

    const int b = blockIdx.x;
    const int t = threadIdx.x;
    const int w = t >> 5, lane = t & 31;
    const int wg = w & 7, ih = w >> 3;  // split-K halves for 8-row-per-warp GEMMs

    // ---- P0: gather x = emb[inputs[b]] ----
    #pragma unroll
    for (int r = 0; r < 4; r++) {
        int row = w * 4 + r;
        int idx = __ldg(inputs + b * LLN + row);
        float4 v = __ldg((const float4*)(emb + (size_t)idx * DD) + lane);
        *((float4*)(xs + row * DD) + lane) = v;
    }

    // ---- P1: per-edge node bitmasks ----
    #pragma unroll
    for (int k = 0; k < 8; k++) {
        int e = w * 8 + k;
        const float* hr = HT + ((size_t)b * NEE + e) * LLN;
        float h0 = __ldg(hr + lane), h1 = __ldg(hr + lane + 32);
        unsigned m0 = __ballot_sync(0xffffffffu, h0 > 0.f);
        unsigned m1 = __ballot_sync(0xffffffffu, h1 > 0.f);
        if (lane == 0) adjm[e] = ((u64)m1 << 32) | (u64)m0;
    }
    __syncthreads();

    for (int l = 0; l < 2; l++) {
        const float* xtp = xs;

        // ---- transfer GEMM (layer 2): xt = xs @ g2w, split-K, row-pair packed ----
        if (l == 1) {
            {
                const float4* src = (const float4*)g2w;
                float4* dst = (float4*)edge;
                #pragma unroll
                for (int r = 0; r < 8; r++)
                    dst[w * 256 + r * 32 + lane] = __ldg(src + w * 256 + r * 32 + lane);
            }
            __syncthreads();
            const int r0 = wg * 8;
            u64 acc[4][4];
            #pragma unroll
            for (int p = 0; p < 4; p++)
                #pragma unroll
                for (int c = 0; c < 4; c++) acc[p][c] = 0;
            #pragma unroll 2
            for (int kk = 0; kk < 64; kk++) {
                int k = ih * 64 + kk;
                float4 wv = *((const float4*)(edge + k * DD) + lane);
                u64 bw0 = dup2(wv.x), bw1 = dup2(wv.y), bw2 = dup2(wv.z), bw3 = dup2(wv.w);
                #pragma unroll
                for (int p = 0; p < 4; p++) {
                    u64 ap = pk2(xs[(r0 + 2 * p) * DD + k], xs[(r0 + 2 * p + 1) * DD + k]);
                    acc[p][0] = fma2(ap, bw0, acc[p][0]);
                    acc[p][1] = fma2(ap, bw1, acc[p][1]);
                    acc[p][2] = fma2(ap, bw2, acc[p][2]);
                    acc[p][3] = fma2(ap, bw3, acc[p][3]);
                }
            }
            __syncthreads();
            if (ih == 1) {
                #pragma unroll
                for (int p = 0; p < 4; p++)
                    #pragma unroll
                    for (int c = 0; c < 4; c++)
                        scr[wg * 512 + (p * 4 + c) * 32 + lane] = acc[p][c];
            }
            __syncthreads();
            if (ih == 0) {
                #pragma unroll
                for (int p = 0; p < 4; p++) {
                    #pragma unroll
                    for (int c = 0; c < 4; c++)
                        acc[p][c] = add2(acc[p][c], scr[wg * 512 + (p * 4 + c) * 32 + lane]);
                    float2 c0 = unp2(acc[p][0]), c1 = unp2(acc[p][1]);
                    float2 c2 = unp2(acc[p][2]), c3 = unp2(acc[p][3]);
                    *((float4*)(xt + (r0 + 2 * p) * DD) + lane)     = make_float4(c0.x, c1.x, c2.x, c3.x);
                    *((float4*)(xt + (r0 + 2 * p + 1) * DD) + lane) = make_float4(c0.y, c1.y, c2.y, c3.y);
                }
            }
            __syncthreads();
            xtp = xt;
        }

        // ---- P2a: e1[j] = lrelu(qa + xs[j].u1), f1[j] = xs[j].u2 ----
        {
            float4 u1v = ((const float4*)g_u1[l])[lane];
            float4 u2v = ((const float4*)g_u2[l])[lane];
            float qa = g_qa[l];
            #pragma unroll
            for (int r = 0; r < 4; r++) {
                int row = w * 4 + r;
                float4 x4 = *((const float4*)(xs + row * DD) + lane);
                float s1 = x4.x * u1v.x + x4.y * u1v.y + x4.z * u1v.z + x4.w * u1v.w;
                float s2 = x4.x * u2v.x + x4.y * u2v.y + x4.z * u2v.z + x4.w * u2v.w;
                s1 = wredsum(s1);
                s2 = wredsum(s2);
                if (lane == 0) {
                    float v = qa + s1;
                    e1[row] = (v > 0.f) ? v : 0.2f * v;
                    f1[row] = s2;
                }
            }
        }
        __syncthreads();

        // ---- P2b: att_edge softmax -> att1[j][e] (pitch 130) ----
        {
            float ev0 = e1[lane], ev1 = e1[lane + 32];
            #pragma unroll
            for (int k = 0; k < 8; k++) {
                int e = w * 8 + k;
                u64 m = adjm[e];
                float v0 = ((m >> lane) & 1ull) ? ev0 : NEGV;
                float v1 = ((m >> (lane + 32)) & 1ull) ? ev1 : NEGV;
                float mx = wredmax(fmaxf(v0, v1));
                float p0 = __expf(v0 - mx), p1 = __expf(v1 - mx);
                float inv = 1.f / wredsum(p0 + p1);
                att[lane * P1PITCH + e]        = p0 * inv;
                att[(lane + 32) * P1PITCH + e] = p1 * inv;
            }
        }
        __syncthreads();

        // ---- P2c: edge = att_edge @ xtp (row-pair packed), fused f2 = edge . v3 ----
        {
            const int e0 = w * 8;
            u64 acc[4][4];
            #pragma unroll
            for (int p = 0; p < 4; p++)
                #pragma unroll
                for (int c = 0; c < 4; c++) acc[p][c] = 0;
            #pragma unroll 2
            for (int j = 0; j < LLN; j++) {
                float4 vx = *((const float4*)(xtp + j * DD) + lane);
                u64 bx0 = dup2(vx.x), bx1 = dup2(vx.y), bx2 = dup2(vx.z), bx3 = dup2(vx.w);
                const u64* ar = (const u64*)(att + j * P1PITCH + e0);
                u64 a0 = ar[0], a1 = ar[1], a2 = ar[2], a3 = ar[3];
                acc[0][0] = fma2(a0, bx0, acc[0][0]); acc[0][1] = fma2(a0, bx1, acc[0][1]);
                acc[0][2] = fma2(a0, bx2, acc[0][2]); acc[0][3] = fma2(a0, bx3, acc[0][3]);
                acc[1][0] = fma2(a1, bx0, acc[1][0]); acc[1][1] = fma2(a1, bx1, acc[1][1]);
                acc[1][2] = fma2(a1, bx2, acc[1][2]); acc[1][3] = fma2(a1, bx3, acc[1][3]);
                acc[2][0] = fma2(a2, bx0, acc[2][0]); acc[2][1] = fma2(a2, bx1, acc[2][1]);
                acc[2][2] = fma2(a2, bx2, acc[2][2]); acc[2][3] = fma2(a2, bx3, acc[2][3]);
                acc[3][0] = fma2(a3, bx0, acc[3][0]); acc[3][1] = fma2(a3, bx1, acc[3][1]);
                acc[3][2] = fma2(a3, bx2, acc[3][2]); acc[3][3] = fma2(a3, bx3, acc[3][3]);
            }
            float4 v3v = ((const float4*)g_v3[l])[lane];
            u64 v30 = dup2(v3v.x), v31 = dup2(v3v.y), v32 = dup2(v3v.z), v33 = dup2(v3v.w);
            #pragma unroll
            for (int p = 0; p < 4; p++) {
                float2 c0 = unp2(acc[p][0]), c1 = unp2(acc[p][1]);
                float2 c2 = unp2(acc[p][2]), c3 = unp2(acc[p][3]);
                *((float4*)(edge + (e0 + 2 * p) * DD) + lane)     = make_float4(c0.x, c1.x, c2.x, c3.x);
                *((float4*)(edge + (e0 + 2 * p + 1) * DD) + lane) = make_float4(c0.y, c1.y, c2.y, c3.y);
                u64 sv = 0;
                sv = fma2(acc[p][0], v30, sv);
                sv = fma2(acc[p][1], v31, sv);
                sv = fma2(acc[p][2], v32, sv);
                sv = fma2(acc[p][3], v33, sv);
                sv = wredsum2(sv);
                if (lane == 0) {
                    float2 s = unp2(sv);
                    f2[e0 + 2 * p]     = s.x;
                    f2[e0 + 2 * p + 1] = s.y;
                }
            }
        }
        __syncthreads();

        // ---- P2d: att_node softmax -> att2[i][j] (pitch 66) ----
        {
            u64 mk0 = adjm[lane],      mk1 = adjm[lane + 32];
            u64 mk2 = adjm[lane + 64], mk3 = adjm[lane + 96];
            float fv0 = f2[lane], fv1 = f2[lane + 32], fv2 = f2[lane + 64], fv3 = f2[lane + 96];
            #pragma unroll
            for (int r = 0; r < 4; r++) {
                int j = w * 4 + r;
                float f1j = f1[j];
                float z0 = f1j + fv0; z0 = (z0 > 0.f) ? z0 : 0.2f * z0;
                float z1 = f1j + fv1; z1 = (z1 > 0.f) ? z1 : 0.2f * z1;
                float z2 = f1j + fv2; z2 = (z2 > 0.f) ? z2 : 0.2f * z2;
                float z3 = f1j + fv3; z3 = (z3 > 0.f) ? z3 : 0.2f * z3;
                float v0 = ((mk0 >> j) & 1ull) ? z0 : NEGV;
                float v1 = ((mk1 >> j) & 1ull) ? z1 : NEGV;
                float v2 = ((mk2 >> j) & 1ull) ? z2 : NEGV;
                float v3 = ((mk3 >> j) & 1ull) ? z3 : NEGV;
                float mx = wredmax(fmaxf(fmaxf(v0, v1), fmaxf(v2, v3)));
                float p0 = __expf(v0 - mx), p1 = __expf(v1 - mx);
                float p2 = __expf(v2 - mx), p3 = __expf(v3 - mx);
                float inv = 1.f / wredsum(p0 + p1 + p2 + p3);
                att[lane * P2PITCH + j]        = p0 * inv;
                att[(lane + 32) * P2PITCH + j] = p1 * inv;
                att[(lane + 64) * P2PITCH + j] = p2 * inv;
                att[(lane + 96) * P2PITCH + j] = p3 * inv;
            }
        }
        __syncthreads();

        // ---- P2e: x = att_node @ edge + residual ; split-K over edges, row-pair packed ----
        {
            const int j0 = wg * 8;
            u64 acc[4][4];
            #pragma unroll
            for (int p = 0; p < 4; p++)
                #pragma unroll
                for (int c = 0; c < 4; c++) acc[p][c] = 0;
            #pragma unroll 2
            for (int ii = 0; ii < 64; ii++) {
                int i = ih * 64 + ii;
                float4 ev = *((const float4*)(edge + i * DD) + lane);
                u64 be0 = dup2(ev.x), be1 = dup2(ev.y), be2 = dup2(ev.z), be3 = dup2(ev.w);
                const u64* ar = (const u64*)(att + i * P2PITCH + j0);
                u64 a0 = ar[0], a1 = ar[1], a2 = ar[2], a3 = ar[3];
                acc[0][0] = fma2(a0, be0, acc[0][0]); acc[0][1] = fma2(a0, be1, acc[0][1]);
                acc[0][2] = fma2(a0, be2, acc[0][2]); acc[0][3] = fma2(a0, be3, acc[0][3]);
                acc[1][0] = fma2(a1, be0, acc[1][0]); acc[1][1] = fma2(a1, be1, acc[1][1]);
                acc[1][2] = fma2(a1, be2, acc[1][2]); acc[1][3] = fma2(a1, be3, acc[1][3]);
                acc[2][0] = fma2(a2, be0, acc[2][0]); acc[2][1] = fma2(a2, be1, acc[2][1]);
                acc[2][2] = fma2(a2, be2, acc[2][2]); acc[2][3] = fma2(a2, be3, acc[2][3]);
                acc[3][0] = fma2(a3, be0, acc[3][0]); acc[3][1] = fma2(a3, be1, acc[3][1]);
                acc[3][2] = fma2(a3, be2, acc[3][2]); acc[3][3] = fma2(a3, be3, acc[3][3]);
            }
            __syncthreads();
            if (ih == 1) {
                #pragma unroll
                for (int p = 0; p < 4; p++)
                    #pragma unroll
                    for (int c = 0; c < 4; c++)
                        scr[wg * 512 + (p * 4 + c) * 32 + lane] = acc[p][c];
            }
            __syncthreads();
            if (ih == 0) {
                #pragma unroll
                for (int p = 0; p < 4; p++) {
                    #pragma unroll
                    for (int c = 0; c < 4; c++)
                        acc[p][c] = add2(acc[p][c], scr[wg * 512 + (p * 4 + c) * 32 + lane]);
                    int ra = j0 + 2 * p, rb = ra + 1;
                    int ia = __ldg(inputs + b * LLN + ra);
                    int ib2 = __ldg(inputs + b * LLN + rb);
                    float4 ga = __ldg((const float4*)(emb + (size_t)ia * DD) + lane);
                    float4 gb = __ldg((const float4*)(emb + (size_t)ib2 * DD) + lane);
                    float2 c0 = unp2(acc[p][0]), c1 = unp2(acc[p][1]);
                    float2 c2 = unp2(acc[p][2]), c3 = unp2(acc[p][3]);
                    *((float4*)(xs + ra * DD) + lane) =
                        make_float4(c0.x + ga.x, c1.x + ga.y, c2.x + ga.z, c3.x + ga.w);
                    *((float4*)(xs + rb * DD) + lane) =
                        make_float4(c0.y + gb.x, c1.y + gb.y, c2.y + gb.z, c3.y + gb.w);
                }
            }
            __syncthreads();
        }
    }

    // ---- outputs: x, x, emb2[inputs] ----
    #pragma unroll
    for (int r = 0; r < 4; r++) {
        int row = w * 4 + r;
        size_t base = ((size_t)b * LLN + row) * (size_t)DD + lane * 4;
        float4 v = *((const float4*)(xs + row * DD) + lane);
        *(float4*)(out + base) = v;
        *(float4*)(out + NOUT + base) = v;
        int idx = __ldg(inputs + b * LLN + row);
        float4 g = __ldg((const float4*)(emb2 + (size_t)idx * DD) + lane);
        *(float4*)(out + 2 * NOUT + base) = g;
    }
}

extern "C" void kernel_launch(void* const* d_in, const int* in_sizes, int n_in,
                              void* d_out, int out_size) {
    (void)in_sizes; (void)n_in; (void)out_size;
    const int*   inputs = (const int*)  d_in[0];
    const float* HT     = (const float*)d_in[1];
    const float* emb    = (const float*)d_in[4];
    const float* emb2   = (const float*)d_in[5];
    const float* g1_w2  = (const float*)d_in[6];
    const float* g1_w3  = (const float*)d_in[7];
    const float* g1_q   = (const float*)d_in[8];
    const float* g1_a   = (const float*)d_in[9];
    const float* g1_a2  = (const float*)d_in[10];
    const float* g2_w   = (const float*)d_in[11];
    const float* g2_w2  = (const float*)d_in[12];
    const float* g2_w3  = (const float*)d_in[13];
    const float* g2_q   = (const float*)d_in[14];
    const float* g2_a   = (const float*)d_in[15];
    const float* g2_a2  = (const float*)d_in[16];
    float* out = (float*)d_out;

    cudaFuncSetAttribute(session_main, cudaFuncAttributeMaxDynamicSharedMemorySize, SMEM_BYTES);

    precompute_kernel<<<1, 128>>>(g1_w2, g1_w3, g1_q, g1_a, g1_a2,
                                  g2_w2, g2_w3, g2_q, g2_a, g2_a2);
    session_main<<<BB, 512, SMEM_BYTES>>>(inputs, HT, emb, emb2, g2_w, out);
}